// round 15
// baseline (speedup 1.0000x reference)
#include <cuda_runtime.h>
#include <cuda_fp16.h>
#include <cstdint>

#define NN   50000
#define EE   1600000
#define MT64 782              // ceil(50000/64)

// ---------------- scratch (static device globals) ---------------------------
__device__ __align__(256) float g_b0[(size_t)NN * 128];
__device__ __align__(256) float g_b1[(size_t)NN * 128];
__device__ __align__(256) __half g_ah[(size_t)NN * 256];
__device__ __align__(256) __half g_bwh[4 * 128 * 256];    // splits of 16*W
__device__ __align__(256) __half g_bwl[4 * 128 * 256];
__device__ int g_deg[NN];
__device__ int g_rowptr[NN + 1];
__device__ int g_pos[NN];
__device__ int g_col[EE];
__device__ __align__(16) float g_stats[1024];     // 4 sets x (sum[128], ss[128])

#define WSCALE_INV 0.0625f    // weights stored as 16*W; epilogue rescales

// ---------------- small PTX helpers ------------------------------------------
__device__ __forceinline__ uint32_t s2u(const void* p) {
    uint32_t a;
    asm("{ .reg .u64 t; cvta.to.shared.u64 t, %1; cvt.u32.u64 %0, t; }"
        : "=r"(a) : "l"(p));
    return a;
}

#define LDSM4(r, addr)                                                         \
    asm volatile("ldmatrix.sync.aligned.m8n8.x4.shared.b16 {%0,%1,%2,%3}, [%4];" \
                 : "=r"((r)[0]), "=r"((r)[1]), "=r"((r)[2]), "=r"((r)[3])      \
                 : "r"(addr))

__device__ __forceinline__ void mma16816(float* c, const uint32_t* a,
                                         uint32_t b0, uint32_t b1) {
    asm volatile(
        "mma.sync.aligned.m16n8k16.row.col.f32.f16.f16.f32 "
        "{%0,%1,%2,%3}, {%4,%5,%6,%7}, {%8,%9}, {%0,%1,%2,%3};"
        : "+f"(c[0]), "+f"(c[1]), "+f"(c[2]), "+f"(c[3])
        : "r"(a[0]), "r"(a[1]), "r"(a[2]), "r"(a[3]), "r"(b0), "r"(b1));
}

__device__ __forceinline__ void cp16(uint32_t saddr, const void* g, int sz) {
    asm volatile("cp.async.cg.shared.global [%0], [%1], 16, %2;"
                 :: "r"(saddr), "l"(g), "r"(sz));
}
__device__ __forceinline__ void cp_commit() {
    asm volatile("cp.async.commit_group;");
}

// ---------------- fp16 helpers -------------------------------------------------
__device__ __forceinline__ uint32_t cvt2h(float lo, float hi) {
    uint32_t r;
    asm("cvt.rn.f16x2.f32 %0, %1, %2;" : "=r"(r) : "f"(hi), "f"(lo));
    return r;
}
__device__ __forceinline__ uint2 quant4(float4 v) {
    uint2 h;
    h.x = cvt2h(v.x, v.y);
    h.y = cvt2h(v.z, v.w);
    return h;
}

// per-CTA BN finalize: scale/shift from raw (biasless) stats
__device__ __forceinline__ void compute_affine_smem(
    float* s_sc, float* s_sh,
    const float* __restrict__ st, const float* __restrict__ bias,
    const float* __restrict__ g, const float* __restrict__ be) {
    int c = threadIdx.x;
    if (c < 128) {
        const float invM = 1.0f / (float)NN;
        float mean_raw = st[c] * invM;
        float var = fmaf(-mean_raw, mean_raw, st[128 + c] * invM);
        float mean = mean_raw + bias[c];
        float r = rsqrtf(var + 1e-5f);
        float sc = g[c] * r;
        s_sc[c] = sc;
        s_sh[c] = be[c] - mean * sc;
    }
    __syncthreads();
}

// ---------------- weight prep (+ stats zero) ----------------------------------
__global__ void prep_w(const float* __restrict__ Wi, const float* __restrict__ Wh,
                       const float* __restrict__ Wl1, const float* __restrict__ Wr1,
                       const float* __restrict__ Wl2, const float* __restrict__ Wr2) {
    if (blockIdx.x < 4) g_stats[blockIdx.x * 256 + threadIdx.x] = 0.f;
    int t = blockIdx.x * blockDim.x + threadIdx.x;
    int mat = t >> 15;
    int r = t & 32767;
    int n = r >> 8;
    int k = r & 255;
    float v = 0.f;
    if (mat == 0) v = Wi[k * 128 + n];
    else if (mat == 1) { if (k < 128) v = Wh[k * 128 + n]; }
    else if (mat == 2) v = (k < 128) ? Wl1[k * 128 + n] : Wr1[(k - 128) * 128 + n];
    else               v = (k < 128) ? Wl2[k * 128 + n] : Wr2[(k - 128) * 128 + n];
    float v16 = v * 16.0f;
    __half h = __float2half_rn(v16);
    float res = v16 - __half2float(h);
    g_bwh[mat * 32768 + n * 256 + k] = h;
    g_bwl[mat * 32768 + n * 256 + k] = __float2half_rn(res);
}

// ---------------- shared MMA pieces (BM=64, 128 threads, 4 warps) --------------
// A block: 4KB per 32-col chunk (row*64 + swizzle). B block: Bh@0, Bl@+8192.
__device__ __forceinline__ void mma_stage(uint32_t a_base, uint32_t b_base,
                                          int lane, int wm, int wn,
                                          float (&acc)[2][8][4]) {
#pragma unroll
    for (int k16 = 0; k16 < 2; k16++) {
        int g = lane >> 3;
        uint32_t ah_r[2][4], b_r[4][4];
#pragma unroll
        for (int mf = 0; mf < 2; mf++) {
            int row = wm * 32 + mf * 16 + ((g & 1) << 3) + (lane & 7);
            int c = k16 * 2 + (g >> 1);
            LDSM4(ah_r[mf], a_base + row * 64 + ((c ^ (row & 3)) << 4));
        }
#pragma unroll
        for (int nf = 0; nf < 4; nf++) {
            int row = wn * 64 + nf * 16 + ((g >> 1) << 3) + (lane & 7);
            int c = k16 * 2 + (g & 1);
            LDSM4(b_r[nf], b_base + row * 64 + ((c ^ (row & 3)) << 4));
        }
#pragma unroll
        for (int mf = 0; mf < 2; mf++)
#pragma unroll
            for (int nf = 0; nf < 4; nf++) {
                mma16816(acc[mf][nf * 2],     ah_r[mf], b_r[nf][0], b_r[nf][1]);
                mma16816(acc[mf][nf * 2 + 1], ah_r[mf], b_r[nf][2], b_r[nf][3]);
            }
#pragma unroll
        for (int nf = 0; nf < 4; nf++) {
            int row = wn * 64 + nf * 16 + ((g >> 1) << 3) + (lane & 7);
            int c = k16 * 2 + (g & 1);
            LDSM4(b_r[nf], b_base + 8192 + row * 64 + ((c ^ (row & 3)) << 4));
        }
#pragma unroll
        for (int mf = 0; mf < 2; mf++)
#pragma unroll
            for (int nf = 0; nf < 4; nf++) {
                mma16816(acc[mf][nf * 2],     ah_r[mf], b_r[nf][0], b_r[nf][1]);
                mma16816(acc[mf][nf * 2 + 1], ah_r[mf], b_r[nf][2], b_r[nf][3]);
            }
    }
}

// B tile: 128 rows x 32 halves -> Bh@b_base, Bl@b_base+8192.
__device__ __forceinline__ void issue_b(const __half* __restrict__ bh,
                                        const __half* __restrict__ bl,
                                        uint32_t b_base, int kk, int tid) {
#pragma unroll
    for (int i = 0; i < 4; i++) {
        int unit = tid + i * 128;
        int row = unit >> 2, c = unit & 3;
        uint32_t off = row * 64 + ((c ^ (row & 3)) << 4);
        cp16(b_base + off, bh + (size_t)row * 256 + kk * 32 + c * 8, 16);
        cp16(b_base + 8192 + off, bl + (size_t)row * 256 + kk * 32 + c * 8, 16);
    }
}

// epilogue: C = acc/16 + bias (fp32), fused BIASLESS col-stats.
__device__ __forceinline__ void gemm_epilogue(
    float (&acc)[2][8][4], const float* __restrict__ bias, float* __restrict__ C,
    float* __restrict__ st, float* smem_stat, int m0, int lane, int wm, int wn,
    int tid) {
#pragma unroll
    for (int nf8 = 0; nf8 < 8; nf8++) {
        int col = wn * 64 + nf8 * 8 + (lane & 3) * 2;
        float bx = __ldg(bias + col);
        float by = __ldg(bias + col + 1);
        float s0 = 0.f, q0 = 0.f, s1 = 0.f, q1 = 0.f;
#pragma unroll
        for (int mf = 0; mf < 2; mf++) {
            float v0 = acc[mf][nf8][0] * WSCALE_INV;
            float v1 = acc[mf][nf8][1] * WSCALE_INV;
            float v2 = acc[mf][nf8][2] * WSCALE_INV;
            float v3 = acc[mf][nf8][3] * WSCALE_INV;
            s0 += v0 + v2; q0 += v0 * v0 + v2 * v2;
            s1 += v1 + v3; q1 += v1 * v1 + v3 * v3;
            int r0 = m0 + wm * 32 + mf * 16 + (lane >> 2);
            if (r0 < NN)
                *(float2*)(C + (size_t)r0 * 128 + col) = make_float2(v0 + bx, v1 + by);
            int r1 = r0 + 8;
            if (r1 < NN)
                *(float2*)(C + (size_t)r1 * 128 + col) = make_float2(v2 + bx, v3 + by);
        }
#pragma unroll
        for (int msk = 4; msk < 32; msk <<= 1) {
            s0 += __shfl_xor_sync(0xffffffffu, s0, msk);
            q0 += __shfl_xor_sync(0xffffffffu, q0, msk);
            s1 += __shfl_xor_sync(0xffffffffu, s1, msk);
            q1 += __shfl_xor_sync(0xffffffffu, q1, msk);
        }
        if ((lane >> 2) == 0) {
            atomicAdd(&smem_stat[col], s0);
            atomicAdd(&smem_stat[col + 1], s1);
            atomicAdd(&smem_stat[128 + col], q0);
            atomicAdd(&smem_stat[128 + col + 1], q1);
        }
    }
    __syncthreads();
#pragma unroll
    for (int i = tid; i < 256; i += 128) atomicAdd(st + i, smem_stat[i]);
}

// ---------------- fused SAGE GEMM: in-kernel gather + K=256 MMA ------------------
// smem: AGG(16K)@0 | AFULL(16K)@16K | 3 B-stages(16K)@32K | stat(1K)@80K
#define AGG_OFF   0
#define AFULL_OFF 16384
#define SSTG_OFF  32768
#define SSTG      16384
#define GSMEM_SAGE (32768 + 3 * SSTG + 1024)

// self-branch A (cols [128:256)) bulk load: 1024 16B-units / 128 thr = 8 iters.
__device__ __forceinline__ void issue_a_full(const __half* __restrict__ ah,
                                             uint32_t sb, int m0, int tid) {
#pragma unroll
    for (int i = 0; i < 8; i++) {
        int unit = tid + i * 128;
        int row = unit >> 4, c16 = unit & 15;
        int kkc = c16 >> 2, cc = c16 & 3;
        uint32_t off = AFULL_OFF + kkc * 4096 + row * 64 + ((cc ^ (row & 3)) << 4);
        int grow = m0 + row;
        int ok = grow < NN;
        cp16(sb + off, ah + (size_t)(ok ? grow : 0) * 256 + 128 + c16 * 8,
             ok ? 16 : 0);
    }
}

__global__ void __launch_bounds__(128, 2) gemm_sage(
    const __half* __restrict__ ah,
    const __half* __restrict__ bh, const __half* __restrict__ bl,
    const float* __restrict__ bias, float* __restrict__ C,
    float* __restrict__ st)
{
    extern __shared__ char smem[];
    const uint32_t sb = s2u(smem);
    float* smem_stat = (float*)(smem + SSTG_OFF + 3 * SSTG);
    const int tid = threadIdx.x;
    const int lane = tid & 31;
    const int wid = tid >> 5;
    const int wm = wid & 1;
    const int wn = wid >> 1;
    const int m0 = blockIdx.x * 64;

    smem_stat[tid] = 0.f;
    smem_stat[tid + 128] = 0.f;

    float acc[2][8][4];
#pragma unroll
    for (int i = 0; i < 2; i++)
#pragma unroll
        for (int j = 0; j < 8; j++)
#pragma unroll
            for (int q = 0; q < 4; q++) acc[i][j][q] = 0.f;

    // kick off async loads (overlap the gather below)
    issue_a_full(ah, sb, m0, tid);
    issue_b(bh, bl, sb + SSTG_OFF, 0, tid);
    cp_commit();                               // G1: AFULL + B0
    issue_b(bh, bl, sb + SSTG_OFF + SSTG, 1, tid);
    cp_commit();                               // G2: B1

    // ---- gather: mean over neighbors of this CTA's 64 rows -> AGG smem ----
    // warp wid handles rows wid*16 .. wid*16+15; lane covers cols lane*4..+3.
    {
        int kkc = lane >> 3, c2 = lane & 7;
        for (int i = 0; i < 16; i++) {
            int row = wid * 16 + i;
            int node = m0 + row;
            float a0 = 0.f, a1 = 0.f, a2 = 0.f, a3 = 0.f;
            float inv = 1.f;
            if (node < NN) {
                int beg = g_rowptr[node], end = g_rowptr[node + 1];
                int e = beg;
                for (; e + 8 <= end; e += 8) {
                    int sidx[8];
                    uint2 vv[8];
#pragma unroll
                    for (int j = 0; j < 8; j++) sidx[j] = __ldg(&g_col[e + j]);
#pragma unroll
                    for (int j = 0; j < 8; j++)
                        vv[j] = __ldg((const uint2*)(ah + (size_t)sidx[j] * 256 +
                                                     128 + lane * 4));
#pragma unroll
                    for (int j = 0; j < 8; j++) {
                        float2 p0 = __half22float2(*(__half2*)&vv[j].x);
                        float2 p1 = __half22float2(*(__half2*)&vv[j].y);
                        a0 += p0.x; a1 += p0.y; a2 += p1.x; a3 += p1.y;
                    }
                }
                for (; e < end; e++) {
                    int s = __ldg(&g_col[e]);
                    uint2 v = __ldg((const uint2*)(ah + (size_t)s * 256 + 128 +
                                                   lane * 4));
                    float2 p0 = __half22float2(*(__half2*)&v.x);
                    float2 p1 = __half22float2(*(__half2*)&v.y);
                    a0 += p0.x; a1 += p0.y; a2 += p1.x; a3 += p1.y;
                }
                int d = end - beg;
                inv = 1.0f / (float)(d > 0 ? d : 1);
            }
            float4 m = make_float4(a0 * inv, a1 * inv, a2 * inv, a3 * inv);
            uint32_t off = AGG_OFF + kkc * 4096 + row * 64 +
                           (((c2 >> 1) ^ (row & 3)) << 4) + ((c2 & 1) << 3);
            *(uint2*)(smem + off) = quant4(m);
        }
    }

    // ---- mainloop: kk<4 A from AGG, kk>=4 A from AFULL; B 3-stage pipeline ----
    for (int kk = 0; kk < 8; kk++) {
        if (kk < 7) asm volatile("cp.async.wait_group 1;");
        else        asm volatile("cp.async.wait_group 0;");
        __syncthreads();
        if (kk + 2 < 8) {
            issue_b(bh, bl, sb + SSTG_OFF + ((kk + 2) % 3) * SSTG, kk + 2, tid);
            cp_commit();
        }
        uint32_t a_base = (kk < 4) ? sb + AGG_OFF + kk * 4096
                                   : sb + AFULL_OFF + (kk - 4) * 4096;
        mma_stage(a_base, sb + SSTG_OFF + (kk % 3) * SSTG, lane, wm, wn, acc);
        __syncthreads();
    }
    gemm_epilogue(acc, bias, C, st, smem_stat, m0, lane, wm, wn, tid);
}

// ---------------- GEMM, fp32 A (in-kernel quantize, optional fused BN+ReLU) ----
// MODE 0: K=256, A = fp32 rows of 256 (x), no affine            [layer 1]
// MODE 1: K=128, A = fp32 rows of 128, affine+relu (BN1)        [layer 2]
// stage layout (20KB): A@0 (4K), Bh@4K, Bl@12K.
#define STG64 20480
#define GSMEM_MIX (2 * STG64 + 2048)

template <int MODE>
__global__ void __launch_bounds__(128, 3) gemm_mix(
    const float* __restrict__ Af,
    const __half* __restrict__ bh, const __half* __restrict__ bl,
    const float* __restrict__ bias, float* __restrict__ C, float* __restrict__ st,
    const float* __restrict__ a_st, const float* __restrict__ a_bias,
    const float* __restrict__ a_g, const float* __restrict__ a_be)
{
    constexpr int K = (MODE == 1) ? 128 : 256;
    constexpr int nk = K >> 5;
    constexpr int AST = (MODE == 0) ? 256 : 128;
    extern __shared__ char smem[];
    const uint32_t sb = s2u(smem);
    float* smem_stat = (float*)(smem + 2 * STG64);
    float* s_sc = smem_stat + 256;
    float* s_sh = smem_stat + 384;
    const int tid = threadIdx.x;
    const int lane = tid & 31;
    const int wid = tid >> 5;
    const int wm = wid & 1;
    const int wn = wid >> 1;
    const int m0 = blockIdx.x * 64;

    smem_stat[tid] = 0.f;
    smem_stat[tid + 128] = 0.f;
    if constexpr (MODE != 0) {
        compute_affine_smem(s_sc, s_sh, a_st, a_bias, a_g, a_be);
    }

    float acc[2][8][4];
#pragma unroll
    for (int i = 0; i < 2; i++)
#pragma unroll
        for (int j = 0; j < 8; j++)
#pragma unroll
            for (int q = 0; q < 4; q++) acc[i][j][q] = 0.f;

    uint2 hreg[4];
    auto lda = [&](int kk) {
#pragma unroll
        for (int i = 0; i < 4; i++) {
            int unit = tid + i * 128;
            int row = unit >> 3, c = unit & 7;
            int grow = m0 + row;
            bool ok = grow < NN;
            int kcol = kk * 32 + c * 4;
            float4 v = make_float4(0.f, 0.f, 0.f, 0.f);
            if (ok)
                v = __ldg((const float4*)(Af + (size_t)grow * AST + kcol));
            if (MODE != 0) {
                float4 sc = *((const float4*)s_sc + (kcol >> 2));
                float4 sh = *((const float4*)s_sh + (kcol >> 2));
                v.x = fmaf(v.x, sc.x, sh.x);
                v.y = fmaf(v.y, sc.y, sh.y);
                v.z = fmaf(v.z, sc.z, sh.z);
                v.w = fmaf(v.w, sc.w, sh.w);
                if (MODE == 1) {
                    v.x = fmaxf(v.x, 0.f);
                    v.y = fmaxf(v.y, 0.f);
                    v.z = fmaxf(v.z, 0.f);
                    v.w = fmaxf(v.w, 0.f);
                }
                // re-zero OOB rows AFTER the affine (guarded C-store,
                // unguarded fused stats).
                if (!ok) v = make_float4(0.f, 0.f, 0.f, 0.f);
            }
            hreg[i] = quant4(v);
        }
    };
    auto sts = [&](uint32_t base) {
#pragma unroll
        for (int i = 0; i < 4; i++) {
            int unit = tid + i * 128;
            int row = unit >> 3, c = unit & 7;
            uint32_t off = row * 64 + ((((c >> 1) ^ (row & 3))) << 4) + ((c & 1) << 3);
            *(uint2*)(smem + (base - sb) + off) = hreg[i];
        }
    };

    lda(0);
    issue_b(bh, bl, sb + 4096, 0, tid);
    cp_commit();
    sts(sb);
    if (nk > 1) lda(1);

    for (int kk = 0; kk < nk; kk++) {
        asm volatile("cp.async.wait_group 0;");
        __syncthreads();
        uint32_t nbase = sb + ((kk + 1) & 1) * STG64;
        if (kk + 1 < nk) {
            issue_b(bh, bl, nbase + 4096, kk + 1, tid);
            cp_commit();
            sts(nbase);
        }
        if (kk + 2 < nk) lda(kk + 2);
        uint32_t cbase = sb + (kk & 1) * STG64;
        mma_stage(cbase, cbase + 4096, lane, wm, wn, acc);
        __syncthreads();
    }
    gemm_epilogue(acc, bias, C, st, smem_stat, m0, lane, wm, wn, tid);
}

// ---------------- BN apply (per-CTA finalize) -----------------------------------
template <bool RELU, bool WF32, bool WH16>
__global__ void bn_apply(const float4* __restrict__ X, float4* __restrict__ Y,
                         int colofs, int n4,
                         const float* __restrict__ st, const float* __restrict__ bias,
                         const float* __restrict__ g, const float* __restrict__ be) {
    __shared__ __align__(16) float s_sc[128];
    __shared__ __align__(16) float s_sh[128];
    compute_affine_smem(s_sc, s_sh, st, bias, g, be);
    int i = blockIdx.x * blockDim.x + threadIdx.x;
    if (i >= n4) return;
    int gsel = i & 31;
    float4 sc = *((const float4*)s_sc + gsel);
    float4 sh = *((const float4*)s_sh + gsel);
    float4 v = X[i];
    float4 r;
    r.x = fmaf(v.x, sc.x, sh.x);
    r.y = fmaf(v.y, sc.y, sh.y);
    r.z = fmaf(v.z, sc.z, sh.z);
    r.w = fmaf(v.w, sc.w, sh.w);
    if (RELU) {
        r.x = fmaxf(r.x, 0.f);
        r.y = fmaxf(r.y, 0.f);
        r.z = fmaxf(r.z, 0.f);
        r.w = fmaxf(r.w, 0.f);
    }
    if (WF32) Y[i] = r;
    if (WH16) {
        int row = i >> 5;
        int c = (i & 31) * 4;
        *(uint2*)(g_ah + (size_t)row * 256 + colofs + c) = quant4(r);
    }
}

// ---------------- CSR build -----------------------------------------------------
__global__ void zero_deg() {
    int i = blockIdx.x * blockDim.x + threadIdx.x;
    if (i < NN) g_deg[i] = 0;
}

__global__ void count_deg(const int* __restrict__ dst) {
    for (int e = blockIdx.x * blockDim.x + threadIdx.x; e < EE;
         e += gridDim.x * blockDim.x)
        atomicAdd(&g_deg[__ldg(&dst[e])], 1);
}

__global__ void __launch_bounds__(1024, 1) scan_deg() {
    __shared__ int wsum[32];
    int tid = threadIdx.x, lane = tid & 31, wid = tid >> 5;
    const int CH = (NN + 1023) >> 10;
    int start = tid * CH;
    int arr[49];
#pragma unroll
    for (int i = 0; i < 49; i++) {
        int idx = start + i;
        arr[i] = (idx < NN) ? g_deg[idx] : 0;
    }
    int s = 0;
#pragma unroll
    for (int i = 0; i < 49; i++) s += arr[i];
    int v = s;
#pragma unroll
    for (int off = 1; off < 32; off <<= 1) {
        int t = __shfl_up_sync(0xffffffffu, v, off);
        if (lane >= off) v += t;
    }
    if (lane == 31) wsum[wid] = v;
    __syncthreads();
    if (wid == 0) {
        int w = wsum[lane];
#pragma unroll
        for (int off = 1; off < 32; off <<= 1) {
            int t = __shfl_up_sync(0xffffffffu, w, off);
            if (lane >= off) w += t;
        }
        wsum[lane] = w;
    }
    __syncthreads();
    int run = (wid ? wsum[wid - 1] : 0) + (v - s);
#pragma unroll
    for (int i = 0; i < 49; i++) {
        int idx = start + i;
        if (idx < NN) {
            g_rowptr[idx] = run;
            g_pos[idx] = run;
            run += arr[i];
        }
    }
    if (tid == 1023) g_rowptr[NN] = run;
}

__global__ void fill_csr(const int* __restrict__ src, const int* __restrict__ dst) {
    for (int e = blockIdx.x * blockDim.x + threadIdx.x; e < EE;
         e += gridDim.x * blockDim.x) {
        int d = __ldg(&dst[e]);
        int p = atomicAdd(&g_pos[d], 1);
        g_col[p] = __ldg(&src[e]);
    }
}

// ---------------- launch ---------------------------------------------------------
extern "C" void kernel_launch(void* const* d_in, const int* in_sizes, int n_in,
                              void* d_out, int out_size) {
    const float* x     = (const float*)d_in[0];
    const int*   ei    = (const int*)d_in[1];
    const float* W_in  = (const float*)d_in[2];
    const float* b_in  = (const float*)d_in[3];
    const float* g1    = (const float*)d_in[4];
    const float* be1   = (const float*)d_in[5];
    const float* W_hid = (const float*)d_in[6];
    const float* b_hid = (const float*)d_in[7];
    const float* g2    = (const float*)d_in[8];
    const float* be2   = (const float*)d_in[9];
    const float* Wl1   = (const float*)d_in[10];
    const float* bl1   = (const float*)d_in[11];
    const float* Wr1   = (const float*)d_in[12];
    const float* g3    = (const float*)d_in[13];
    const float* be3   = (const float*)d_in[14];
    const float* Wl2   = (const float*)d_in[15];
    const float* bl2   = (const float*)d_in[16];
    const float* Wr2   = (const float*)d_in[17];
    const float* g4    = (const float*)d_in[18];
    const float* be4   = (const float*)d_in[19];

    const int* src = ei;
    const int* dst = ei + EE;
    float* out_feat = (float*)d_out;
    float* out_out  = out_feat + (size_t)NN * 128;

    void *p0, *p1, *pah, *pbh, *pbl, *pst;
    cudaGetSymbolAddress(&p0, g_b0);
    cudaGetSymbolAddress(&p1, g_b1);
    cudaGetSymbolAddress(&pah, g_ah);
    cudaGetSymbolAddress(&pbh, g_bwh);
    cudaGetSymbolAddress(&pbl, g_bwl);
    cudaGetSymbolAddress(&pst, g_stats);
    float* b0 = (float*)p0;
    float* b1 = (float*)p1;
    __half* ah = (__half*)pah;
    __half* bwh = (__half*)pbh;
    __half* bwl = (__half*)pbl;
    float* st = (float*)pst;

    static cudaStream_t s_csr = nullptr;
    static cudaEvent_t ev_fork = nullptr, ev_csr = nullptr;
    static bool setup_done = false;
    if (!setup_done) {
        cudaFuncSetAttribute(gemm_sage, cudaFuncAttributeMaxDynamicSharedMemorySize,
                             GSMEM_SAGE);
        cudaFuncSetAttribute(gemm_mix<0>,
                             cudaFuncAttributeMaxDynamicSharedMemorySize, GSMEM_MIX);
        cudaFuncSetAttribute(gemm_mix<1>,
                             cudaFuncAttributeMaxDynamicSharedMemorySize, GSMEM_MIX);
        cudaStreamCreateWithFlags(&s_csr, cudaStreamNonBlocking);
        cudaEventCreateWithFlags(&ev_fork, cudaEventDisableTiming);
        cudaEventCreateWithFlags(&ev_csr, cudaEventDisableTiming);
        setup_done = true;
    }

    const int n4 = NN * 32;
    const int gBN = (n4 + 255) / 256;

    // ---- fork: CSR build on side stream ----
    cudaEventRecord(ev_fork, 0);
    cudaStreamWaitEvent(s_csr, ev_fork, 0);
    zero_deg<<<(NN + 255) / 256, 256, 0, s_csr>>>();
    count_deg<<<4096, 256, 0, s_csr>>>(dst);
    scan_deg<<<1, 1024, 0, s_csr>>>();
    fill_csr<<<4096, 256, 0, s_csr>>>(src, dst);
    cudaEventRecord(ev_csr, s_csr);

    // ---- main stream ----
    prep_w<<<512, 256>>>(W_in, W_hid, Wl1, Wr1, Wl2, Wr2);

    // layer 1: raw1 = x @ W_in + b_in (stats fused)
    gemm_mix<0><<<MT64, 128, GSMEM_MIX>>>(x, bwh, bwl, b_in, b0, st, x, x, x, x);
    // layer 2: raw2 = relu(BN1(raw1)) @ W_hid + b_hid (BN1 fused in A-load)
    gemm_mix<1><<<MT64, 128, GSMEM_MIX>>>(b0, bwh + 32768, bwl + 32768, b_hid,
                                          b1, st + 256, st, b_in, g1, be1);
    // feat = relu(BN2(raw2)) -> out_feat fp32 + fp16 [128:256)
    bn_apply<true, true, true><<<gBN, 256>>>((const float4*)b1, (float4*)out_feat,
                                             128, n4, st + 256, b_hid, g2, be2);

    // ---- join CSR before first fused SAGE ----
    cudaStreamWaitEvent(0, ev_csr, 0);

    // SAGE 1: fused gather(feat fp16 [128:256)) + GEMM -> raw3 fp32 b0
    gemm_sage<<<MT64, 128, GSMEM_SAGE>>>(ah, bwh + 2 * 32768, bwl + 2 * 32768,
                                         bl1, b0, st + 512);
    // o3 = BN3(raw3) -> fp16 [128:256) for SAGE2 gather + self-branch
    bn_apply<false, false, true><<<gBN, 256>>>((const float4*)b0, nullptr, 128, n4,
                                               st + 512, bl1, g3, be3);

    // SAGE 2: fused gather(o3) + GEMM -> raw4 fp32 b1
    gemm_sage<<<MT64, 128, GSMEM_SAGE>>>(ah, bwh + 3 * 32768, bwl + 3 * 32768,
                                         bl2, b1, st + 768);
    // out = BN4(raw4) -> out_out fp32
    bn_apply<false, true, false><<<gBN, 256>>>((const float4*)b1, (float4*)out_out,
                                               0, n4, st + 768, bl2, g4, be4);
}

// round 16
// speedup vs baseline: 1.7220x; 1.7220x over previous
#include <cuda_runtime.h>
#include <cuda_fp16.h>
#include <cstdint>

#define NN   50000
#define EE   1600000
#define MT64 782              // ceil(50000/64)

// ---------------- scratch (static device globals) ---------------------------
__device__ __align__(256) float g_b0[(size_t)NN * 128];
__device__ __align__(256) float g_b1[(size_t)NN * 128];
__device__ __align__(256) __half g_ah[(size_t)NN * 256];
__device__ __align__(256) __half g_bwh[4 * 128 * 256];    // splits of 16*W
__device__ __align__(256) __half g_bwl[4 * 128 * 256];
__device__ int g_deg[NN];
__device__ int g_rowptr[NN + 1];
__device__ int g_pos[NN];
__device__ int g_col[EE];
__device__ __align__(16) float g_stats[1024];     // 4 sets x (sum[128], ss[128])

#define WSCALE_INV 0.0625f    // weights stored as 16*W; epilogue rescales

// ---------------- small PTX helpers ------------------------------------------
__device__ __forceinline__ uint32_t s2u(const void* p) {
    uint32_t a;
    asm("{ .reg .u64 t; cvta.to.shared.u64 t, %1; cvt.u32.u64 %0, t; }"
        : "=r"(a) : "l"(p));
    return a;
}

#define LDSM4(r, addr)                                                         \
    asm volatile("ldmatrix.sync.aligned.m8n8.x4.shared.b16 {%0,%1,%2,%3}, [%4];" \
                 : "=r"((r)[0]), "=r"((r)[1]), "=r"((r)[2]), "=r"((r)[3])      \
                 : "r"(addr))

__device__ __forceinline__ void mma16816(float* c, const uint32_t* a,
                                         uint32_t b0, uint32_t b1) {
    asm volatile(
        "mma.sync.aligned.m16n8k16.row.col.f32.f16.f16.f32 "
        "{%0,%1,%2,%3}, {%4,%5,%6,%7}, {%8,%9}, {%0,%1,%2,%3};"
        : "+f"(c[0]), "+f"(c[1]), "+f"(c[2]), "+f"(c[3])
        : "r"(a[0]), "r"(a[1]), "r"(a[2]), "r"(a[3]), "r"(b0), "r"(b1));
}

__device__ __forceinline__ void cp16(uint32_t saddr, const void* g, int sz) {
    asm volatile("cp.async.cg.shared.global [%0], [%1], 16, %2;"
                 :: "r"(saddr), "l"(g), "r"(sz));
}
__device__ __forceinline__ void cp_commit() {
    asm volatile("cp.async.commit_group;");
}

// ---------------- fp16 helpers -------------------------------------------------
__device__ __forceinline__ uint32_t cvt2h(float lo, float hi) {
    uint32_t r;
    asm("cvt.rn.f16x2.f32 %0, %1, %2;" : "=r"(r) : "f"(hi), "f"(lo));
    return r;
}
__device__ __forceinline__ uint2 quant4(float4 v) {
    uint2 h;
    h.x = cvt2h(v.x, v.y);
    h.y = cvt2h(v.z, v.w);
    return h;
}

// per-CTA BN finalize: scale/shift from raw (biasless) stats
__device__ __forceinline__ void compute_affine_smem(
    float* s_sc, float* s_sh,
    const float* __restrict__ st, const float* __restrict__ bias,
    const float* __restrict__ g, const float* __restrict__ be) {
    int c = threadIdx.x;
    if (c < 128) {
        const float invM = 1.0f / (float)NN;
        float mean_raw = st[c] * invM;
        float var = fmaf(-mean_raw, mean_raw, st[128 + c] * invM);
        float mean = mean_raw + bias[c];
        float r = rsqrtf(var + 1e-5f);
        float sc = g[c] * r;
        s_sc[c] = sc;
        s_sh[c] = be[c] - mean * sc;
    }
    __syncthreads();
}

// ---------------- weight prep (+ stats zero) ----------------------------------
__global__ void prep_w(const float* __restrict__ Wi, const float* __restrict__ Wh,
                       const float* __restrict__ Wl1, const float* __restrict__ Wr1,
                       const float* __restrict__ Wl2, const float* __restrict__ Wr2) {
    if (blockIdx.x < 4) g_stats[blockIdx.x * 256 + threadIdx.x] = 0.f;
    int t = blockIdx.x * blockDim.x + threadIdx.x;
    int mat = t >> 15;
    int r = t & 32767;
    int n = r >> 8;
    int k = r & 255;
    float v = 0.f;
    if (mat == 0) v = Wi[k * 128 + n];
    else if (mat == 1) { if (k < 128) v = Wh[k * 128 + n]; }
    else if (mat == 2) v = (k < 128) ? Wl1[k * 128 + n] : Wr1[(k - 128) * 128 + n];
    else               v = (k < 128) ? Wl2[k * 128 + n] : Wr2[(k - 128) * 128 + n];
    float v16 = v * 16.0f;
    __half h = __float2half_rn(v16);
    float res = v16 - __half2float(h);
    g_bwh[mat * 32768 + n * 256 + k] = h;
    g_bwl[mat * 32768 + n * 256 + k] = __float2half_rn(res);
}

// ---------------- shared GEMM pieces (BM=64, 128 threads, 4 warps) -------------
// stage layout (20KB): Ah@0 (4K), Bh@4K (8K), Bl@12K (8K).
#define STG64 20480
#define OFF_BH 4096
#define OFF_BL 12288

__device__ __forceinline__ void mma_stage(uint32_t base, int lane, int wm, int wn,
                                          float (&acc)[2][8][4]) {
#pragma unroll
    for (int k16 = 0; k16 < 2; k16++) {
        int g = lane >> 3;
        uint32_t ah_r[2][4], b_r[4][4];
#pragma unroll
        for (int mf = 0; mf < 2; mf++) {
            int row = wm * 32 + mf * 16 + ((g & 1) << 3) + (lane & 7);
            int c = k16 * 2 + (g >> 1);
            LDSM4(ah_r[mf], base + row * 64 + ((c ^ (row & 3)) << 4));
        }
#pragma unroll
        for (int nf = 0; nf < 4; nf++) {
            int row = wn * 64 + nf * 16 + ((g >> 1) << 3) + (lane & 7);
            int c = k16 * 2 + (g & 1);
            LDSM4(b_r[nf], base + OFF_BH + row * 64 + ((c ^ (row & 3)) << 4));
        }
#pragma unroll
        for (int mf = 0; mf < 2; mf++)
#pragma unroll
            for (int nf = 0; nf < 4; nf++) {
                mma16816(acc[mf][nf * 2],     ah_r[mf], b_r[nf][0], b_r[nf][1]);
                mma16816(acc[mf][nf * 2 + 1], ah_r[mf], b_r[nf][2], b_r[nf][3]);
            }
#pragma unroll
        for (int nf = 0; nf < 4; nf++) {
            int row = wn * 64 + nf * 16 + ((g >> 1) << 3) + (lane & 7);
            int c = k16 * 2 + (g & 1);
            LDSM4(b_r[nf], base + OFF_BL + row * 64 + ((c ^ (row & 3)) << 4));
        }
#pragma unroll
        for (int mf = 0; mf < 2; mf++)
#pragma unroll
            for (int nf = 0; nf < 4; nf++) {
                mma16816(acc[mf][nf * 2],     ah_r[mf], b_r[nf][0], b_r[nf][1]);
                mma16816(acc[mf][nf * 2 + 1], ah_r[mf], b_r[nf][2], b_r[nf][3]);
            }
    }
}

// B tile: 128 rows x 32 halves. 512 16B-units / 128 threads = 4 iters.
__device__ __forceinline__ void issue_b(const __half* __restrict__ bh,
                                        const __half* __restrict__ bl,
                                        uint32_t base, int kk, int tid) {
#pragma unroll
    for (int i = 0; i < 4; i++) {
        int unit = tid + i * 128;
        int row = unit >> 2, c = unit & 3;
        uint32_t off = row * 64 + ((c ^ (row & 3)) << 4);
        cp16(base + OFF_BH + off, bh + (size_t)row * 256 + kk * 32 + c * 8, 16);
        cp16(base + OFF_BL + off, bl + (size_t)row * 256 + kk * 32 + c * 8, 16);
    }
}

// epilogue: C = acc/16 + bias (fp32), fused BIASLESS col-stats.
__device__ __forceinline__ void gemm_epilogue(
    float (&acc)[2][8][4], const float* __restrict__ bias, float* __restrict__ C,
    float* __restrict__ st, float* smem_stat, int m0, int lane, int wm, int wn,
    int tid) {
#pragma unroll
    for (int nf8 = 0; nf8 < 8; nf8++) {
        int col = wn * 64 + nf8 * 8 + (lane & 3) * 2;
        float bx = __ldg(bias + col);
        float by = __ldg(bias + col + 1);
        float s0 = 0.f, q0 = 0.f, s1 = 0.f, q1 = 0.f;
#pragma unroll
        for (int mf = 0; mf < 2; mf++) {
            float v0 = acc[mf][nf8][0] * WSCALE_INV;
            float v1 = acc[mf][nf8][1] * WSCALE_INV;
            float v2 = acc[mf][nf8][2] * WSCALE_INV;
            float v3 = acc[mf][nf8][3] * WSCALE_INV;
            s0 += v0 + v2; q0 += v0 * v0 + v2 * v2;
            s1 += v1 + v3; q1 += v1 * v1 + v3 * v3;
            int r0 = m0 + wm * 32 + mf * 16 + (lane >> 2);
            if (r0 < NN)
                *(float2*)(C + (size_t)r0 * 128 + col) = make_float2(v0 + bx, v1 + by);
            int r1 = r0 + 8;
            if (r1 < NN)
                *(float2*)(C + (size_t)r1 * 128 + col) = make_float2(v2 + bx, v3 + by);
        }
#pragma unroll
        for (int msk = 4; msk < 32; msk <<= 1) {
            s0 += __shfl_xor_sync(0xffffffffu, s0, msk);
            q0 += __shfl_xor_sync(0xffffffffu, q0, msk);
            s1 += __shfl_xor_sync(0xffffffffu, s1, msk);
            q1 += __shfl_xor_sync(0xffffffffu, q1, msk);
        }
        if ((lane >> 2) == 0) {
            atomicAdd(&smem_stat[col], s0);
            atomicAdd(&smem_stat[col + 1], s1);
            atomicAdd(&smem_stat[128 + col], q0);
            atomicAdd(&smem_stat[128 + col + 1], q1);
        }
    }
    __syncthreads();
#pragma unroll
    for (int i = tid; i < 256; i += 128) atomicAdd(st + i, smem_stat[i]);
}

// ---------------- GEMM, fp16 A via cp.async (3-stage) — SAGE1/SAGE2 ------------
#define GSMEM_STD (3 * STG64 + 1024)

// A tile: 64 rows x 32 halves. 256 16B-units / 128 threads = 2 iters.
__device__ __forceinline__ void issue_a_h(const __half* __restrict__ ah,
                                          uint32_t base, int kk, int m0, int tid) {
#pragma unroll
    for (int i = 0; i < 2; i++) {
        int unit = tid + i * 128;
        int row = unit >> 2, c = unit & 3;
        uint32_t off = row * 64 + ((c ^ (row & 3)) << 4);
        int grow = m0 + row;
        int ok = grow < NN;
        size_t gofs = (size_t)(ok ? grow : 0) * 256 + kk * 32 + c * 8;
        cp16(base + off, ah + gofs, ok ? 16 : 0);
    }
}

__global__ void __launch_bounds__(128, 3) gemm_bf(
    const __half* __restrict__ ah,
    const __half* __restrict__ bh, const __half* __restrict__ bl,
    const float* __restrict__ bias, float* __restrict__ C,
    float* __restrict__ st, int K)
{
    extern __shared__ char smem[];
    const uint32_t sb = s2u(smem);
    float* smem_stat = (float*)(smem + 3 * STG64);
    const int tid = threadIdx.x;
    const int lane = tid & 31;
    const int wid = tid >> 5;
    const int wm = wid & 1;
    const int wn = wid >> 1;
    const int m0 = blockIdx.x * 64;
    const int nk = K >> 5;

    smem_stat[tid] = 0.f;
    smem_stat[tid + 128] = 0.f;

    float acc[2][8][4];
#pragma unroll
    for (int i = 0; i < 2; i++)
#pragma unroll
        for (int j = 0; j < 8; j++)
#pragma unroll
            for (int q = 0; q < 4; q++) acc[i][j][q] = 0.f;

    issue_a_h(ah, sb, 0, m0, tid);
    issue_b(bh, bl, sb, 0, tid);
    cp_commit();
    issue_a_h(ah, sb + STG64, 1, m0, tid);
    issue_b(bh, bl, sb + STG64, 1, tid);
    cp_commit();

    for (int kk = 0; kk < nk; kk++) {
        if (kk < nk - 1) asm volatile("cp.async.wait_group 1;");
        else             asm volatile("cp.async.wait_group 0;");
        __syncthreads();
        if (kk + 2 < nk) {
            uint32_t base = sb + ((kk + 2) % 3) * STG64;
            issue_a_h(ah, base, kk + 2, m0, tid);
            issue_b(bh, bl, base, kk + 2, tid);
            cp_commit();
        }
        mma_stage(sb + (kk % 3) * STG64, lane, wm, wn, acc);
        __syncthreads();
    }
    gemm_epilogue(acc, bias, C, st, smem_stat, m0, lane, wm, wn, tid);
}

// ---------------- GEMM, fp32 A (in-kernel quantize, optional fused BN+ReLU) ----
// MODE 0: K=256, A = fp32 rows of 256 (x), no affine            [layer 1]
// MODE 1: K=128, A = fp32 rows of 128, affine+relu (BN1)        [layer 2]
#define GSMEM_MIX (2 * STG64 + 2048)

template <int MODE>
__global__ void __launch_bounds__(128, 3) gemm_mix(
    const float* __restrict__ Af,
    const __half* __restrict__ bh, const __half* __restrict__ bl,
    const float* __restrict__ bias, float* __restrict__ C, float* __restrict__ st,
    const float* __restrict__ a_st, const float* __restrict__ a_bias,
    const float* __restrict__ a_g, const float* __restrict__ a_be)
{
    constexpr int K = (MODE == 1) ? 128 : 256;
    constexpr int nk = K >> 5;
    constexpr int AST = (MODE == 0) ? 256 : 128;
    extern __shared__ char smem[];
    const uint32_t sb = s2u(smem);
    float* smem_stat = (float*)(smem + 2 * STG64);
    float* s_sc = smem_stat + 256;
    float* s_sh = smem_stat + 384;
    const int tid = threadIdx.x;
    const int lane = tid & 31;
    const int wid = tid >> 5;
    const int wm = wid & 1;
    const int wn = wid >> 1;
    const int m0 = blockIdx.x * 64;

    smem_stat[tid] = 0.f;
    smem_stat[tid + 128] = 0.f;
    if constexpr (MODE != 0) {
        compute_affine_smem(s_sc, s_sh, a_st, a_bias, a_g, a_be);
    }

    float acc[2][8][4];
#pragma unroll
    for (int i = 0; i < 2; i++)
#pragma unroll
        for (int j = 0; j < 8; j++)
#pragma unroll
            for (int q = 0; q < 4; q++) acc[i][j][q] = 0.f;

    uint2 hreg[4];
    auto lda = [&](int kk) {
#pragma unroll
        for (int i = 0; i < 4; i++) {
            int unit = tid + i * 128;
            int row = unit >> 3, c = unit & 7;
            int grow = m0 + row;
            bool ok = grow < NN;
            int kcol = kk * 32 + c * 4;
            float4 v = make_float4(0.f, 0.f, 0.f, 0.f);
            if (ok)
                v = __ldg((const float4*)(Af + (size_t)grow * AST + kcol));
            if (MODE != 0) {
                float4 sc = *((const float4*)s_sc + (kcol >> 2));
                float4 sh = *((const float4*)s_sh + (kcol >> 2));
                v.x = fmaf(v.x, sc.x, sh.x);
                v.y = fmaf(v.y, sc.y, sh.y);
                v.z = fmaf(v.z, sc.z, sh.z);
                v.w = fmaf(v.w, sc.w, sh.w);
                if (MODE == 1) {
                    v.x = fmaxf(v.x, 0.f);
                    v.y = fmaxf(v.y, 0.f);
                    v.z = fmaxf(v.z, 0.f);
                    v.w = fmaxf(v.w, 0.f);
                }
                // re-zero OOB rows AFTER the affine (guarded C-store,
                // unguarded fused stats).
                if (!ok) v = make_float4(0.f, 0.f, 0.f, 0.f);
            }
            hreg[i] = quant4(v);
        }
    };
    auto sts = [&](uint32_t base) {
#pragma unroll
        for (int i = 0; i < 4; i++) {
            int unit = tid + i * 128;
            int row = unit >> 3, c = unit & 7;
            uint32_t off = row * 64 + ((((c >> 1) ^ (row & 3))) << 4) + ((c & 1) << 3);
            *(uint2*)(smem + (base - sb) + off) = hreg[i];
        }
    };

    lda(0);
    issue_b(bh, bl, sb, 0, tid);
    cp_commit();
    sts(sb);
    if (nk > 1) lda(1);

    for (int kk = 0; kk < nk; kk++) {
        asm volatile("cp.async.wait_group 0;");
        __syncthreads();
        uint32_t nbase = sb + ((kk + 1) & 1) * STG64;
        if (kk + 1 < nk) {
            issue_b(bh, bl, nbase, kk + 1, tid);
            cp_commit();
            sts(nbase);
        }
        if (kk + 2 < nk) lda(kk + 2);
        mma_stage(sb + (kk & 1) * STG64, lane, wm, wn, acc);
        __syncthreads();
    }
    gemm_epilogue(acc, bias, C, st, smem_stat, m0, lane, wm, wn, tid);
}

// ---------------- BN apply (per-CTA finalize) -----------------------------------
template <bool RELU, bool WF32, bool WH16>
__global__ void bn_apply(const float4* __restrict__ X, float4* __restrict__ Y,
                         int colofs, int n4,
                         const float* __restrict__ st, const float* __restrict__ bias,
                         const float* __restrict__ g, const float* __restrict__ be) {
    __shared__ __align__(16) float s_sc[128];
    __shared__ __align__(16) float s_sh[128];
    compute_affine_smem(s_sc, s_sh, st, bias, g, be);
    int i = blockIdx.x * blockDim.x + threadIdx.x;
    if (i >= n4) return;
    int gsel = i & 31;
    float4 sc = *((const float4*)s_sc + gsel);
    float4 sh = *((const float4*)s_sh + gsel);
    float4 v = X[i];
    float4 r;
    r.x = fmaf(v.x, sc.x, sh.x);
    r.y = fmaf(v.y, sc.y, sh.y);
    r.z = fmaf(v.z, sc.z, sh.z);
    r.w = fmaf(v.w, sc.w, sh.w);
    if (RELU) {
        r.x = fmaxf(r.x, 0.f);
        r.y = fmaxf(r.y, 0.f);
        r.z = fmaxf(r.z, 0.f);
        r.w = fmaxf(r.w, 0.f);
    }
    if (WF32) Y[i] = r;
    if (WH16) {
        int row = i >> 5;
        int c = (i & 31) * 4;
        *(uint2*)(g_ah + (size_t)row * 256 + colofs + c) = quant4(r);
    }
}

// ---------------- CSR build -----------------------------------------------------
__global__ void zero_deg() {
    int i = blockIdx.x * blockDim.x + threadIdx.x;
    if (i < NN) g_deg[i] = 0;
}

__global__ void count_deg(const int* __restrict__ dst) {
    for (int e = blockIdx.x * blockDim.x + threadIdx.x; e < EE;
         e += gridDim.x * blockDim.x)
        atomicAdd(&g_deg[__ldg(&dst[e])], 1);
}

__global__ void __launch_bounds__(1024, 1) scan_deg() {
    __shared__ int wsum[32];
    int tid = threadIdx.x, lane = tid & 31, wid = tid >> 5;
    const int CH = (NN + 1023) >> 10;
    int start = tid * CH;
    int arr[49];
#pragma unroll
    for (int i = 0; i < 49; i++) {
        int idx = start + i;
        arr[i] = (idx < NN) ? g_deg[idx] : 0;
    }
    int s = 0;
#pragma unroll
    for (int i = 0; i < 49; i++) s += arr[i];
    int v = s;
#pragma unroll
    for (int off = 1; off < 32; off <<= 1) {
        int t = __shfl_up_sync(0xffffffffu, v, off);
        if (lane >= off) v += t;
    }
    if (lane == 31) wsum[wid] = v;
    __syncthreads();
    if (wid == 0) {
        int w = wsum[lane];
#pragma unroll
        for (int off = 1; off < 32; off <<= 1) {
            int t = __shfl_up_sync(0xffffffffu, w, off);
            if (lane >= off) w += t;
        }
        wsum[lane] = w;
    }
    __syncthreads();
    int run = (wid ? wsum[wid - 1] : 0) + (v - s);
#pragma unroll
    for (int i = 0; i < 49; i++) {
        int idx = start + i;
        if (idx < NN) {
            g_rowptr[idx] = run;
            g_pos[idx] = run;
            run += arr[i];
        }
    }
    if (tid == 1023) g_rowptr[NN] = run;
}

__global__ void fill_csr(const int* __restrict__ src, const int* __restrict__ dst) {
    for (int e = blockIdx.x * blockDim.x + threadIdx.x; e < EE;
         e += gridDim.x * blockDim.x) {
        int d = __ldg(&dst[e]);
        int p = atomicAdd(&g_pos[d], 1);
        g_col[p] = __ldg(&src[e]);
    }
}

// ---------------- SAGE mean aggregation (reads g_ah cols [128:256)) ------------
// one warp per node; explicit 8-wide batching for MLP (order-preserving).
__global__ void sage_agg_h() {
    int gw = (blockIdx.x * blockDim.x + threadIdx.x) >> 5;
    int lane = threadIdx.x & 31;
    if (gw >= NN) return;
    int beg = g_rowptr[gw], end = g_rowptr[gw + 1];
    float a0 = 0.f, a1 = 0.f, a2 = 0.f, a3 = 0.f;
    int e = beg;
    for (; e + 8 <= end; e += 8) {
        int sidx[8];
        uint2 vv[8];
#pragma unroll
        for (int j = 0; j < 8; j++) sidx[j] = __ldg(&g_col[e + j]);
#pragma unroll
        for (int j = 0; j < 8; j++)
            vv[j] = __ldg((const uint2*)(g_ah + (size_t)sidx[j] * 256 + 128 +
                                         lane * 4));
#pragma unroll
        for (int j = 0; j < 8; j++) {
            float2 p0 = __half22float2(*(__half2*)&vv[j].x);
            float2 p1 = __half22float2(*(__half2*)&vv[j].y);
            a0 += p0.x; a1 += p0.y; a2 += p1.x; a3 += p1.y;
        }
    }
    for (; e < end; e++) {
        int s = __ldg(&g_col[e]);
        uint2 v = __ldg((const uint2*)(g_ah + (size_t)s * 256 + 128 + lane * 4));
        float2 p0 = __half22float2(*(__half2*)&v.x);
        float2 p1 = __half22float2(*(__half2*)&v.y);
        a0 += p0.x; a1 += p0.y; a2 += p1.x; a3 += p1.y;
    }
    int d = end - beg;
    float inv = 1.0f / (float)(d > 0 ? d : 1);
    float4 acc = make_float4(a0 * inv, a1 * inv, a2 * inv, a3 * inv);
    *(uint2*)(g_ah + (size_t)gw * 256 + lane * 4) = quant4(acc);
}

// ---------------- launch ---------------------------------------------------------
extern "C" void kernel_launch(void* const* d_in, const int* in_sizes, int n_in,
                              void* d_out, int out_size) {
    const float* x     = (const float*)d_in[0];
    const int*   ei    = (const int*)d_in[1];
    const float* W_in  = (const float*)d_in[2];
    const float* b_in  = (const float*)d_in[3];
    const float* g1    = (const float*)d_in[4];
    const float* be1   = (const float*)d_in[5];
    const float* W_hid = (const float*)d_in[6];
    const float* b_hid = (const float*)d_in[7];
    const float* g2    = (const float*)d_in[8];
    const float* be2   = (const float*)d_in[9];
    const float* Wl1   = (const float*)d_in[10];
    const float* bl1   = (const float*)d_in[11];
    const float* Wr1   = (const float*)d_in[12];
    const float* g3    = (const float*)d_in[13];
    const float* be3   = (const float*)d_in[14];
    const float* Wl2   = (const float*)d_in[15];
    const float* bl2   = (const float*)d_in[16];
    const float* Wr2   = (const float*)d_in[17];
    const float* g4    = (const float*)d_in[18];
    const float* be4   = (const float*)d_in[19];

    const int* src = ei;
    const int* dst = ei + EE;
    float* out_feat = (float*)d_out;
    float* out_out  = out_feat + (size_t)NN * 128;

    void *p0, *p1, *pah, *pbh, *pbl, *pst;
    cudaGetSymbolAddress(&p0, g_b0);
    cudaGetSymbolAddress(&p1, g_b1);
    cudaGetSymbolAddress(&pah, g_ah);
    cudaGetSymbolAddress(&pbh, g_bwh);
    cudaGetSymbolAddress(&pbl, g_bwl);
    cudaGetSymbolAddress(&pst, g_stats);
    float* b0 = (float*)p0;
    float* b1 = (float*)p1;
    __half* ah = (__half*)pah;
    __half* bwh = (__half*)pbh;
    __half* bwl = (__half*)pbl;
    float* st = (float*)pst;

    static cudaStream_t s_csr = nullptr;
    static cudaEvent_t ev_fork = nullptr, ev_csr = nullptr;
    static bool setup_done = false;
    if (!setup_done) {
        cudaFuncSetAttribute(gemm_bf, cudaFuncAttributeMaxDynamicSharedMemorySize,
                             GSMEM_STD);
        cudaFuncSetAttribute(gemm_mix<0>,
                             cudaFuncAttributeMaxDynamicSharedMemorySize, GSMEM_MIX);
        cudaFuncSetAttribute(gemm_mix<1>,
                             cudaFuncAttributeMaxDynamicSharedMemorySize, GSMEM_MIX);
        cudaStreamCreateWithFlags(&s_csr, cudaStreamNonBlocking);
        cudaEventCreateWithFlags(&ev_fork, cudaEventDisableTiming);
        cudaEventCreateWithFlags(&ev_csr, cudaEventDisableTiming);
        setup_done = true;
    }

    const int n4 = NN * 32;
    const int gBN = (n4 + 255) / 256;

    // ---- fork: CSR build on side stream ----
    cudaEventRecord(ev_fork, 0);
    cudaStreamWaitEvent(s_csr, ev_fork, 0);
    zero_deg<<<(NN + 255) / 256, 256, 0, s_csr>>>();
    count_deg<<<4096, 256, 0, s_csr>>>(dst);
    scan_deg<<<1, 1024, 0, s_csr>>>();
    fill_csr<<<4096, 256, 0, s_csr>>>(src, dst);
    cudaEventRecord(ev_csr, s_csr);

    // ---- main stream ----
    prep_w<<<512, 256>>>(W_in, W_hid, Wl1, Wr1, Wl2, Wr2);

    // layer 1: raw1 = x @ W_in + b_in (stats fused)
    gemm_mix<0><<<MT64, 128, GSMEM_MIX>>>(x, bwh, bwl, b_in, b0, st, x, x, x, x);
    // layer 2: raw2 = relu(BN1(raw1)) @ W_hid + b_hid (BN1 fused in A-load)
    gemm_mix<1><<<MT64, 128, GSMEM_MIX>>>(b0, bwh + 32768, bwl + 32768, b_hid,
                                          b1, st + 256, st, b_in, g1, be1);
    // feat = relu(BN2(raw2)) -> out_feat fp32 + fp16 [128:256)
    bn_apply<true, true, true><<<gBN, 256>>>((const float4*)b1, (float4*)out_feat,
                                             128, n4, st + 256, b_hid, g2, be2);

    // ---- join CSR before first aggregation ----
    cudaStreamWaitEvent(0, ev_csr, 0);

    // SAGE 1: agg feat [128:256) -> [0:128); GEMM raw3 -> fp32 b0
    sage_agg_h<<<(NN * 32 + 255) / 256, 256>>>();
    gemm_bf<<<MT64, 128, GSMEM_STD>>>(ah, bwh + 2 * 32768, bwl + 2 * 32768,
                                      bl1, b0, st + 512, 256);
    // o3 = BN3(raw3) -> fp16 [128:256) for agg #2 and SAGE2 self-branch
    bn_apply<false, false, true><<<gBN, 256>>>((const float4*)b0, nullptr, 128, n4,
                                               st + 512, bl1, g3, be3);

    // SAGE 2: agg o3 -> [0:128); GEMM reads full [0:256)
    sage_agg_h<<<(NN * 32 + 255) / 256, 256>>>();
    gemm_bf<<<MT64, 128, GSMEM_STD>>>(ah, bwh + 3 * 32768, bwl + 3 * 32768,
                                      bl2, b1, st + 768, 256);
    // out = BN4(raw4) -> out_out fp32
    bn_apply<false, true, false><<<gBN, 256>>>((const float4*)b1, (float4*)out_out,
                                               0, n4, st + 768, bl2, g4, be4);
}